// round 13
// baseline (speedup 1.0000x reference)
#include <cuda_runtime.h>
#include <cstdint>

// ---------------- problem constants ----------------
#define NMAX 100000
#define EMAX 600000
#define FIN  128
#define FHID 128
#define FOUT 64

// ---------------- scratch (static device globals; zero-initialized at load) ----------------
__device__ __align__(16) float g_hn[(size_t)NMAX * FHID];   // per-layer GEMM out (pre-agg)
__device__ __align__(16) float g_x2[(size_t)NMAX * FHID];   // layer-2 input (tf32-rounded)
__device__ __align__(16) float g_dinv[NMAX];
__device__ __align__(16) float g_w1r[FIN * FHID];           // tf32-rounded W1
__device__ __align__(16) float g_w2r[FHID * FOUT];          // tf32-rounded W2
__device__ int   g_count[NMAX];     // zeroed by k_scan after reading (self-cleaning)
__device__ int   g_start[NMAX];
__device__ int   g_end[NMAX];
__device__ int   g_cursor[NMAX];
__device__ int   g_srcsorted[EMAX];
__device__ int   g_total;           // zeroed by k_fill after scan consumed it

// ---------------- TF32 helpers ----------------
__device__ __forceinline__ float to_tf32(float x) {
    uint32_t u;
    asm("cvt.rna.tf32.f32 %0, %1;" : "=r"(u) : "f"(x));
    return __uint_as_float(u);
}

// ---------------- pre-round weights to tf32 ----------------
__global__ void k_round(const float* __restrict__ W1, const float* __restrict__ W2) {
    int i = blockIdx.x * blockDim.x + threadIdx.x;
    if (i < FIN * FHID) g_w1r[i] = to_tf32(W1[i]);
    if (i < FHID * FOUT) g_w2r[i] = to_tf32(W2[i]);
}

// ---------------- degree / CSR build ----------------
// edge_index is int32, layout [2, E]: src = ei[e], dst = ei[E + e]
__global__ void k_hist(const int* __restrict__ ei, int n_edges, int n_nodes) {
    int e = blockIdx.x * blockDim.x + threadIdx.x;
    if (e < n_edges) {
        int d = ei[n_edges + e];
        if ((unsigned)d < (unsigned)n_nodes) atomicAdd(&g_count[d], 1);
    }
}

// ONE-PASS order-free scan: per-block local prefix + atomic base grab.
// Consumes g_count (re-zeros it for the next replay), writes start/end/cursor/dinv.
__global__ void k_scan(int n) {
    __shared__ int s[256];
    __shared__ int base_sh;
    int t = threadIdx.x;
    int blk = blockIdx.x * 1024;
    int vals[4];
    int tsum = 0;
    #pragma unroll
    for (int k = 0; k < 4; k++) {
        int i = blk + t * 4 + k;
        vals[k] = (i < n) ? g_count[i] : 0;
        tsum += vals[k];
    }
    s[t] = tsum;
    __syncthreads();
    for (int off = 1; off < 256; off <<= 1) {
        int x = (t >= off) ? s[t - off] : 0;
        __syncthreads();
        s[t] += x;
        __syncthreads();
    }
    if (t == 255) base_sh = atomicAdd(&g_total, s[255]);
    __syncthreads();
    int texcl = s[t] - tsum + base_sh;
    int run = 0;
    #pragma unroll
    for (int k = 0; k < 4; k++) {
        int i = blk + t * 4 + k;
        if (i < n) {
            int o = texcl + run;
            g_start[i]  = o;
            g_end[i]    = o + vals[k];
            g_cursor[i] = o;
            g_dinv[i]   = rsqrtf((float)(vals[k] + 1));   // +1 self loop
            g_count[i]  = 0;                              // self-clean for next replay
        }
        run += vals[k];
    }
}

__global__ void k_fill(const int* __restrict__ ei, int n_edges, int n_nodes) {
    int e = blockIdx.x * blockDim.x + threadIdx.x;
    if (e == 0) g_total = 0;        // self-clean (scan already consumed it)
    if (e < n_edges) {
        int srcv = ei[e];
        int d    = ei[n_edges + e];
        if ((unsigned)d < (unsigned)n_nodes && (unsigned)srcv < (unsigned)n_nodes) {
            int p = atomicAdd(&g_cursor[d], 1);
            g_srcsorted[p] = srcv;
        }
    }
}

// ---------------- mma / cp.async helpers ----------------
__device__ __forceinline__ void mma_tf32(float c[4], const float a[4], float b0, float b1) {
    uint32_t const* A = reinterpret_cast<uint32_t const*>(a);
    uint32_t B0 = __float_as_uint(b0), B1 = __float_as_uint(b1);
    asm volatile(
        "mma.sync.aligned.m16n8k8.row.col.f32.tf32.tf32.f32 "
        "{%0,%1,%2,%3}, {%4,%5,%6,%7}, {%8,%9}, {%0,%1,%2,%3};"
        : "+f"(c[0]), "+f"(c[1]), "+f"(c[2]), "+f"(c[3])
        : "r"(A[0]), "r"(A[1]), "r"(A[2]), "r"(A[3]), "r"(B0), "r"(B1));
}

__device__ __forceinline__ void cp_async16(float* smem_ptr, const float* gptr, bool valid) {
    uint32_t sa = (uint32_t)__cvta_generic_to_shared(smem_ptr);
    int sz = valid ? 16 : 0;
    asm volatile("cp.async.cg.shared.global [%0], [%1], 16, %2;"
                 :: "r"(sa), "l"(gptr), "r"(sz));
}
#define CP_COMMIT() asm volatile("cp.async.commit_group;" ::: "memory")
#define CP_WAIT(N)  asm volatile("cp.async.wait_group %0;" :: "n"(N) : "memory")

// ---------------- cp.async double-buffered TF32 GEMM with fused dinv epilogue ----------------
// g_hn[m,n] = g_dinv[m] * sum_k A[m,k]*B[k,n]
// B taken from DEVICE-GLOBAL pre-rounded weights: BN==128 -> g_w1r, BN==64 -> g_w2r.
// ACVT=1: round A fragments in-loop (layer-1 raw x); ACVT=0: A already tf32 (g_x2).
// TM=64 rows/CTA, 8 warps = 2(M) x 4(N), 3 CTAs/SM.
#define KC 32
#define TM 64
#define AP 36
#define ASTRIDE (TM * AP)

template <int BN, int SRC, int ACVT>
__global__ void __launch_bounds__(256, 3)
k_mma_dinv(const float* __restrict__ Aext, int M, int K) {
    const float* __restrict__ A  = (SRC == 0) ? Aext : g_x2;
    const float* __restrict__ Bg = (BN == FHID) ? g_w1r : g_w2r;
    const int BPITCH  = BN + 8;
    const int BSTRIDE = KC * BPITCH;
    const int BTPR    = BN / 4;
    const int BKSTEP  = 256 / BTPR;
    const int NBB     = KC / BKSTEP;

    extern __shared__ float sm[];
    float* As0 = sm;
    float* Bs0 = sm + 2 * ASTRIDE;

    int tid  = threadIdx.x;
    int warp = tid >> 5, lane = tid & 31;
    int wm = warp & 1, wn = warp >> 1;  // 2(M) x 4(N)
    const int WNT = BN / 4;
    const int NF  = WNT / 8;
    int g  = lane >> 2, tg = lane & 3;
    int row0 = blockIdx.x * TM;

    int ar = tid >> 3, ac = (tid & 7) * 4;
    int bkr = tid / BTPR, bbc = (tid % BTPR) * 4;

    auto issue = [&](int kc) {
        float* As = As0 + (kc & 1) * ASTRIDE;
        float* Bs = Bs0 + (kc & 1) * BSTRIDE;
        int k0 = kc * KC;
        #pragma unroll
        for (int i = 0; i < 2; i++) {
            int rr = ar + i * 32;
            cp_async16(&As[rr * AP + ac],
                       A + (size_t)(row0 + rr) * K + k0 + ac,
                       row0 + rr < M);
        }
        #pragma unroll
        for (int i = 0; i < NBB; i++) {
            int kk = bkr + i * BKSTEP;
            cp_async16(&Bs[kk * BPITCH + bbc],
                       Bg + (size_t)(k0 + kk) * BN + bbc, true);
        }
    };

    float acc[2][NF][4];
    #pragma unroll
    for (int i = 0; i < 2; i++)
        #pragma unroll
        for (int j = 0; j < NF; j++)
            #pragma unroll
            for (int q = 0; q < 4; q++) acc[i][j][q] = 0.0f;

    issue(0); CP_COMMIT();

    const int NCHUNK = K / KC;
    for (int kc = 0; kc < NCHUNK; kc++) {
        if (kc + 1 < NCHUNK) { issue(kc + 1); CP_COMMIT(); CP_WAIT(1); }
        else                 { CP_WAIT(0); }
        __syncthreads();

        float* As = As0 + (kc & 1) * ASTRIDE;
        float* Bs = Bs0 + (kc & 1) * BSTRIDE;

        #pragma unroll
        for (int ks = 0; ks < KC; ks += 8) {
            float a[2][4];
            #pragma unroll
            for (int mf = 0; mf < 2; mf++) {
                int arr = wm * 32 + mf * 16;
                a[mf][0] = As[(arr + g)     * AP + ks + tg];
                a[mf][1] = As[(arr + g + 8) * AP + ks + tg];
                a[mf][2] = As[(arr + g)     * AP + ks + tg + 4];
                a[mf][3] = As[(arr + g + 8) * AP + ks + tg + 4];
                if (ACVT) {
                    a[mf][0] = to_tf32(a[mf][0]);
                    a[mf][1] = to_tf32(a[mf][1]);
                    a[mf][2] = to_tf32(a[mf][2]);
                    a[mf][3] = to_tf32(a[mf][3]);
                }
            }
            #pragma unroll
            for (int nf = 0; nf < NF; nf++) {
                int bn0 = wn * WNT + nf * 8;
                float b0 = Bs[(ks + tg)     * BPITCH + bn0 + g];
                float b1 = Bs[(ks + tg + 4) * BPITCH + bn0 + g];
                #pragma unroll
                for (int mf = 0; mf < 2; mf++)
                    mma_tf32(acc[mf][nf], a[mf], b0, b1);
            }
        }
        __syncthreads();
    }

    #pragma unroll
    for (int mf = 0; mf < 2; mf++) {
        int r0 = row0 + wm * 32 + mf * 16 + g;
        int r1 = r0 + 8;
        float d0 = (r0 < M) ? g_dinv[r0] : 0.f;
        float d1 = (r1 < M) ? g_dinv[r1] : 0.f;
        #pragma unroll
        for (int nf = 0; nf < NF; nf++) {
            int cc = wn * WNT + nf * 8 + tg * 2;
            if (r0 < M) {
                g_hn[(size_t)r0 * BN + cc]     = acc[mf][nf][0] * d0;
                g_hn[(size_t)r0 * BN + cc + 1] = acc[mf][nf][1] * d0;
            }
            if (r1 < M) {
                g_hn[(size_t)r1 * BN + cc]     = acc[mf][nf][2] * d1;
                g_hn[(size_t)r1 * BN + cc + 1] = acc[mf][nf][3] * d1;
            }
        }
    }
}

#define SMEM_GEMM(BN) ((2 * ASTRIDE + 2 * KC * ((BN) + 8)) * 4)

// ---------------- aggregation: one warp per node, MLP-4 gathers ----------------
// x2[d] = tf32(relu( dinv[d]*(hn[d] + sum hn[s]) + b1 ))   (F=128, hn pre-scaled)
__global__ void k_agg128(const float* __restrict__ bias, int n_nodes) {
    int warp = (blockIdx.x * blockDim.x + threadIdx.x) >> 5;
    int lane = threadIdx.x & 31;
    if (warp >= n_nodes) return;
    int d = warp;
    const float* hn = g_hn;
    float4 acc = *reinterpret_cast<const float4*>(hn + (size_t)d * 128 + lane * 4);
    float4 acc2 = make_float4(0.f, 0.f, 0.f, 0.f);
    int e = g_start[d], e1 = g_end[d];
    for (; e + 4 <= e1; e += 4) {
        int s0 = g_srcsorted[e],     s1 = g_srcsorted[e + 1];
        int s2 = g_srcsorted[e + 2], s3 = g_srcsorted[e + 3];
        float4 v0 = *reinterpret_cast<const float4*>(hn + (size_t)s0 * 128 + lane * 4);
        float4 v1 = *reinterpret_cast<const float4*>(hn + (size_t)s1 * 128 + lane * 4);
        float4 v2 = *reinterpret_cast<const float4*>(hn + (size_t)s2 * 128 + lane * 4);
        float4 v3 = *reinterpret_cast<const float4*>(hn + (size_t)s3 * 128 + lane * 4);
        acc.x += v0.x; acc.y += v0.y; acc.z += v0.z; acc.w += v0.w;
        acc2.x += v1.x; acc2.y += v1.y; acc2.z += v1.z; acc2.w += v1.w;
        acc.x += v2.x; acc.y += v2.y; acc.z += v2.z; acc.w += v2.w;
        acc2.x += v3.x; acc2.y += v3.y; acc2.z += v3.z; acc2.w += v3.w;
    }
    for (; e < e1; e++) {
        int s = g_srcsorted[e];
        float4 v = *reinterpret_cast<const float4*>(hn + (size_t)s * 128 + lane * 4);
        acc.x += v.x; acc.y += v.y; acc.z += v.z; acc.w += v.w;
    }
    acc.x += acc2.x; acc.y += acc2.y; acc.z += acc2.z; acc.w += acc2.w;
    float dv = g_dinv[d];
    float4 bv = *reinterpret_cast<const float4*>(bias + lane * 4);
    float4 o;
    o.x = to_tf32(fmaxf(fmaf(acc.x, dv, bv.x), 0.f));
    o.y = to_tf32(fmaxf(fmaf(acc.y, dv, bv.y), 0.f));
    o.z = to_tf32(fmaxf(fmaf(acc.z, dv, bv.z), 0.f));
    o.w = to_tf32(fmaxf(fmaf(acc.w, dv, bv.w), 0.f));
    *reinterpret_cast<float4*>(g_x2 + (size_t)d * 128 + lane * 4) = o;
}

// out[d] = dinv[d]*(hn[d] + sum hn[s]) + b2   (F=64, no relu, hn pre-scaled)
__global__ void k_agg64(const float* __restrict__ bias,
                        float* __restrict__ out, int n_nodes) {
    int warp = (blockIdx.x * blockDim.x + threadIdx.x) >> 5;
    int lane = threadIdx.x & 31;
    if (warp >= n_nodes) return;
    int d = warp;
    const float* hn = g_hn;
    float2 acc = *reinterpret_cast<const float2*>(hn + (size_t)d * 64 + lane * 2);
    float2 acc2 = make_float2(0.f, 0.f);
    int e = g_start[d], e1 = g_end[d];
    for (; e + 4 <= e1; e += 4) {
        int s0 = g_srcsorted[e],     s1 = g_srcsorted[e + 1];
        int s2 = g_srcsorted[e + 2], s3 = g_srcsorted[e + 3];
        float2 v0 = *reinterpret_cast<const float2*>(hn + (size_t)s0 * 64 + lane * 2);
        float2 v1 = *reinterpret_cast<const float2*>(hn + (size_t)s1 * 64 + lane * 2);
        float2 v2 = *reinterpret_cast<const float2*>(hn + (size_t)s2 * 64 + lane * 2);
        float2 v3 = *reinterpret_cast<const float2*>(hn + (size_t)s3 * 64 + lane * 2);
        acc.x += v0.x; acc.y += v0.y;
        acc2.x += v1.x; acc2.y += v1.y;
        acc.x += v2.x; acc.y += v2.y;
        acc2.x += v3.x; acc2.y += v3.y;
    }
    for (; e < e1; e++) {
        int s = g_srcsorted[e];
        float2 v = *reinterpret_cast<const float2*>(hn + (size_t)s * 64 + lane * 2);
        acc.x += v.x; acc.y += v.y;
    }
    acc.x += acc2.x; acc.y += acc2.y;
    float dv = g_dinv[d];
    float2 bv = *reinterpret_cast<const float2*>(bias + lane * 2);
    float2 o;
    o.x = fmaf(acc.x, dv, bv.x);
    o.y = fmaf(acc.y, dv, bv.y);
    *reinterpret_cast<float2*>(out + (size_t)d * 64 + lane * 2) = o;
}

// ---------------- launch ----------------
extern "C" void kernel_launch(void* const* d_in, const int* in_sizes, int n_in,
                              void* d_out, int out_size) {
    const float* x  = (const float*)d_in[0];
    const int*   ei = (const int*)d_in[1];     // int32 [2, E]
    const float* W1 = (const float*)d_in[2];
    const float* b1 = (const float*)d_in[3];
    const float* W2 = (const float*)d_in[4];
    const float* b2 = (const float*)d_in[5];
    float* out = (float*)d_out;

    int n_nodes = in_sizes[0] / FIN;       // 100000
    int n_edges = in_sizes[1] / 2;         // 600000

    int nb_edges = (n_edges + 255) / 256;
    int nb_scan  = (n_nodes + 1023) / 1024;
    int nb_gemm  = (n_nodes + TM - 1) / TM;
    int nb_agg   = (n_nodes * 32 + 255) / 256;
    int nb_round = (FIN * FHID + 255) / 256;

    // one-time stream/event/attr setup (first call is the uncaptured correctness run)
    static cudaStream_t s2 = nullptr;
    static cudaEvent_t evF0 = nullptr, evF1 = nullptr, evRound = nullptr, evJoin = nullptr;
    if (!s2) {
        cudaStreamCreateWithFlags(&s2, cudaStreamNonBlocking);
        cudaEventCreateWithFlags(&evF0, cudaEventDisableTiming);
        cudaEventCreateWithFlags(&evF1, cudaEventDisableTiming);
        cudaEventCreateWithFlags(&evRound, cudaEventDisableTiming);
        cudaEventCreateWithFlags(&evJoin, cudaEventDisableTiming);
        cudaFuncSetAttribute(k_mma_dinv<FHID, 0, 1>,
                             cudaFuncAttributeMaxDynamicSharedMemorySize, SMEM_GEMM(FHID));
        cudaFuncSetAttribute(k_mma_dinv<FOUT, 1, 0>,
                             cudaFuncAttributeMaxDynamicSharedMemorySize, SMEM_GEMM(FOUT));
    }

    // ---- side stream: round weights (no deps), later fill (needs scan) ----
    cudaEventRecord(evF0, 0);
    cudaStreamWaitEvent(s2, evF0, 0);
    k_round<<<nb_round, 256, 0, s2>>>(W1, W2);
    cudaEventRecord(evRound, s2);

    // ---- main: CSR hist -> scan ----
    k_hist<<<nb_edges, 256>>>(ei, n_edges, n_nodes);
    k_scan<<<nb_scan, 256>>>(n_nodes);
    cudaEventRecord(evF1, 0);

    // s2: fill overlaps GEMM1
    cudaStreamWaitEvent(s2, evF1, 0);
    k_fill<<<nb_edges, 256, 0, s2>>>(ei, n_edges, n_nodes);
    cudaEventRecord(evJoin, s2);

    // main: GEMM1 (needs dinv from scan + rounded W1)
    cudaStreamWaitEvent(0, evRound, 0);
    k_mma_dinv<FHID, 0, 1><<<nb_gemm, 256, SMEM_GEMM(FHID)>>>(x, n_nodes, FIN);

    cudaStreamWaitEvent(0, evJoin, 0);   // join: adjacency ready

    // ---- layer 1 aggregation ----
    k_agg128<<<nb_agg, 256>>>(b1, n_nodes);

    // ---- layer 2 ----
    k_mma_dinv<FOUT, 1, 0><<<nb_gemm, 256, SMEM_GEMM(FOUT)>>>(nullptr, n_nodes, FHID);
    k_agg64<<<nb_agg, 256>>>(b2, out, n_nodes);
}

// round 14
// speedup vs baseline: 1.3371x; 1.3371x over previous
#include <cuda_runtime.h>
#include <cstdint>

// ---------------- problem constants ----------------
#define NMAX 100000
#define EMAX 600000
#define FIN  128
#define FHID 128
#define FOUT 64

// ---------------- scratch (static device globals; zero-initialized at load) ----------------
__device__ __align__(16) float g_hn[(size_t)NMAX * FHID];   // per-layer GEMM out (pre-agg)
__device__ __align__(16) float g_x2[(size_t)NMAX * FHID];   // layer-2 input (tf32-rounded)
__device__ __align__(16) float g_dinv[NMAX];
__device__ __align__(16) float g_w1r[FIN * FHID];           // tf32-rounded W1
__device__ __align__(16) float g_w2r[FHID * FOUT];          // tf32-rounded W2
__device__ int   g_count[NMAX];     // zeroed by k_scan after reading (self-cleaning)
__device__ int   g_start[NMAX];
__device__ int   g_end[NMAX];
__device__ int   g_cursor[NMAX];
__device__ int   g_srcsorted[EMAX];
__device__ int   g_total;           // zeroed by k_fill after scan consumed it

// ---------------- TF32 helpers ----------------
__device__ __forceinline__ float to_tf32(float x) {
    uint32_t u;
    asm("cvt.rna.tf32.f32 %0, %1;" : "=r"(u) : "f"(x));
    return __uint_as_float(u);
}

// ---------------- pre-round weights to tf32 ----------------
__global__ void k_round(const float* __restrict__ W1, const float* __restrict__ W2) {
    int i = blockIdx.x * blockDim.x + threadIdx.x;
    if (i < FIN * FHID) g_w1r[i] = to_tf32(W1[i]);
    if (i < FHID * FOUT) g_w2r[i] = to_tf32(W2[i]);
}

// ---------------- degree / CSR build ----------------
// edge_index is int32, layout [2, E]: src = ei[e], dst = ei[E + e]
__global__ void k_hist(const int* __restrict__ ei, int n_edges, int n_nodes) {
    int e = blockIdx.x * blockDim.x + threadIdx.x;
    if (e < n_edges) {
        int d = ei[n_edges + e];
        if ((unsigned)d < (unsigned)n_nodes) atomicAdd(&g_count[d], 1);
    }
}

// ONE-PASS order-free scan: per-block local prefix + atomic base grab.
// Consumes g_count (re-zeros it for the next replay), writes start/end/cursor/dinv.
__global__ void k_scan(int n) {
    __shared__ int s[256];
    __shared__ int base_sh;
    int t = threadIdx.x;
    int blk = blockIdx.x * 1024;
    int vals[4];
    int tsum = 0;
    #pragma unroll
    for (int k = 0; k < 4; k++) {
        int i = blk + t * 4 + k;
        vals[k] = (i < n) ? g_count[i] : 0;
        tsum += vals[k];
    }
    s[t] = tsum;
    __syncthreads();
    for (int off = 1; off < 256; off <<= 1) {
        int x = (t >= off) ? s[t - off] : 0;
        __syncthreads();
        s[t] += x;
        __syncthreads();
    }
    if (t == 255) base_sh = atomicAdd(&g_total, s[255]);
    __syncthreads();
    int texcl = s[t] - tsum + base_sh;
    int run = 0;
    #pragma unroll
    for (int k = 0; k < 4; k++) {
        int i = blk + t * 4 + k;
        if (i < n) {
            int o = texcl + run;
            g_start[i]  = o;
            g_end[i]    = o + vals[k];
            g_cursor[i] = o;
            g_dinv[i]   = rsqrtf((float)(vals[k] + 1));   // +1 self loop
            g_count[i]  = 0;                              // self-clean for next replay
        }
        run += vals[k];
    }
}

__global__ void k_fill(const int* __restrict__ ei, int n_edges, int n_nodes) {
    int e = blockIdx.x * blockDim.x + threadIdx.x;
    if (e == 0) g_total = 0;        // self-clean (scan already consumed it)
    if (e < n_edges) {
        int srcv = ei[e];
        int d    = ei[n_edges + e];
        if ((unsigned)d < (unsigned)n_nodes && (unsigned)srcv < (unsigned)n_nodes) {
            int p = atomicAdd(&g_cursor[d], 1);
            g_srcsorted[p] = srcv;
        }
    }
}

// ---------------- mma / cp.async helpers ----------------
__device__ __forceinline__ void mma_tf32(float c[4], const float a[4], float b0, float b1) {
    uint32_t const* A = reinterpret_cast<uint32_t const*>(a);
    uint32_t B0 = __float_as_uint(b0), B1 = __float_as_uint(b1);
    asm volatile(
        "mma.sync.aligned.m16n8k8.row.col.f32.tf32.tf32.f32 "
        "{%0,%1,%2,%3}, {%4,%5,%6,%7}, {%8,%9}, {%0,%1,%2,%3};"
        : "+f"(c[0]), "+f"(c[1]), "+f"(c[2]), "+f"(c[3])
        : "r"(A[0]), "r"(A[1]), "r"(A[2]), "r"(A[3]), "r"(B0), "r"(B1));
}

__device__ __forceinline__ void cp_async16(float* smem_ptr, const float* gptr, bool valid) {
    uint32_t sa = (uint32_t)__cvta_generic_to_shared(smem_ptr);
    int sz = valid ? 16 : 0;
    asm volatile("cp.async.cg.shared.global [%0], [%1], 16, %2;"
                 :: "r"(sa), "l"(gptr), "r"(sz));
}
#define CP_COMMIT() asm volatile("cp.async.commit_group;" ::: "memory")
#define CP_WAIT(N)  asm volatile("cp.async.wait_group %0;" :: "n"(N) : "memory")

// ---------------- cp.async double-buffered TF32 GEMM with fused dinv epilogue ----------------
// g_hn[m,n] = g_dinv[m] * sum_k A[m,k]*B[k,n]
// B from DEVICE-GLOBAL pre-rounded weights: BN==128 -> g_w1r, BN==64 -> g_w2r.
// ACVT=1: round A fragments in-loop (layer-1 raw x); ACVT=0: A already tf32 (g_x2).
// TM=64 rows/CTA, 8 warps = 2(M) x 4(N), 3 CTAs/SM.
#define KC 32
#define TM 64
#define AP 36
#define ASTRIDE (TM * AP)

template <int BN, int SRC, int ACVT>
__global__ void __launch_bounds__(256, 3)
k_mma_dinv(const float* __restrict__ Aext, int M, int K) {
    const float* __restrict__ A  = (SRC == 0) ? Aext : g_x2;
    const float* __restrict__ Bg = (BN == FHID) ? g_w1r : g_w2r;
    const int BPITCH  = BN + 8;
    const int BSTRIDE = KC * BPITCH;
    const int BTPR    = BN / 4;
    const int BKSTEP  = 256 / BTPR;
    const int NBB     = KC / BKSTEP;

    extern __shared__ float sm[];
    float* As0 = sm;
    float* Bs0 = sm + 2 * ASTRIDE;

    int tid  = threadIdx.x;
    int warp = tid >> 5, lane = tid & 31;
    int wm = warp & 1, wn = warp >> 1;  // 2(M) x 4(N)
    const int WNT = BN / 4;
    const int NF  = WNT / 8;
    int g  = lane >> 2, tg = lane & 3;
    int row0 = blockIdx.x * TM;

    int ar = tid >> 3, ac = (tid & 7) * 4;
    int bkr = tid / BTPR, bbc = (tid % BTPR) * 4;

    auto issue = [&](int kc) {
        float* As = As0 + (kc & 1) * ASTRIDE;
        float* Bs = Bs0 + (kc & 1) * BSTRIDE;
        int k0 = kc * KC;
        #pragma unroll
        for (int i = 0; i < 2; i++) {
            int rr = ar + i * 32;
            cp_async16(&As[rr * AP + ac],
                       A + (size_t)(row0 + rr) * K + k0 + ac,
                       row0 + rr < M);
        }
        #pragma unroll
        for (int i = 0; i < NBB; i++) {
            int kk = bkr + i * BKSTEP;
            cp_async16(&Bs[kk * BPITCH + bbc],
                       Bg + (size_t)(k0 + kk) * BN + bbc, true);
        }
    };

    float acc[2][NF][4];
    #pragma unroll
    for (int i = 0; i < 2; i++)
        #pragma unroll
        for (int j = 0; j < NF; j++)
            #pragma unroll
            for (int q = 0; q < 4; q++) acc[i][j][q] = 0.0f;

    issue(0); CP_COMMIT();

    const int NCHUNK = K / KC;
    for (int kc = 0; kc < NCHUNK; kc++) {
        if (kc + 1 < NCHUNK) { issue(kc + 1); CP_COMMIT(); CP_WAIT(1); }
        else                 { CP_WAIT(0); }
        __syncthreads();

        float* As = As0 + (kc & 1) * ASTRIDE;
        float* Bs = Bs0 + (kc & 1) * BSTRIDE;

        #pragma unroll
        for (int ks = 0; ks < KC; ks += 8) {
            float a[2][4];
            #pragma unroll
            for (int mf = 0; mf < 2; mf++) {
                int arr = wm * 32 + mf * 16;
                a[mf][0] = As[(arr + g)     * AP + ks + tg];
                a[mf][1] = As[(arr + g + 8) * AP + ks + tg];
                a[mf][2] = As[(arr + g)     * AP + ks + tg + 4];
                a[mf][3] = As[(arr + g + 8) * AP + ks + tg + 4];
                if (ACVT) {
                    a[mf][0] = to_tf32(a[mf][0]);
                    a[mf][1] = to_tf32(a[mf][1]);
                    a[mf][2] = to_tf32(a[mf][2]);
                    a[mf][3] = to_tf32(a[mf][3]);
                }
            }
            #pragma unroll
            for (int nf = 0; nf < NF; nf++) {
                int bn0 = wn * WNT + nf * 8;
                float b0 = Bs[(ks + tg)     * BPITCH + bn0 + g];
                float b1 = Bs[(ks + tg + 4) * BPITCH + bn0 + g];
                #pragma unroll
                for (int mf = 0; mf < 2; mf++)
                    mma_tf32(acc[mf][nf], a[mf], b0, b1);
            }
        }
        __syncthreads();
    }

    #pragma unroll
    for (int mf = 0; mf < 2; mf++) {
        int r0 = row0 + wm * 32 + mf * 16 + g;
        int r1 = r0 + 8;
        float d0 = (r0 < M) ? g_dinv[r0] : 0.f;
        float d1 = (r1 < M) ? g_dinv[r1] : 0.f;
        #pragma unroll
        for (int nf = 0; nf < NF; nf++) {
            int cc = wn * WNT + nf * 8 + tg * 2;
            if (r0 < M) {
                g_hn[(size_t)r0 * BN + cc]     = acc[mf][nf][0] * d0;
                g_hn[(size_t)r0 * BN + cc + 1] = acc[mf][nf][1] * d0;
            }
            if (r1 < M) {
                g_hn[(size_t)r1 * BN + cc]     = acc[mf][nf][2] * d1;
                g_hn[(size_t)r1 * BN + cc + 1] = acc[mf][nf][3] * d1;
            }
        }
    }
}

#define SMEM_GEMM(BN) ((2 * ASTRIDE + 2 * KC * ((BN) + 8)) * 4)

// ---------------- aggregation: one warp per node, MLP-4 gathers ----------------
// x2[d] = tf32(relu( dinv[d]*(hn[d] + sum hn[s]) + b1 ))   (F=128, hn pre-scaled)
__global__ void k_agg128(const float* __restrict__ bias, int n_nodes) {
    int warp = (blockIdx.x * blockDim.x + threadIdx.x) >> 5;
    int lane = threadIdx.x & 31;
    if (warp >= n_nodes) return;
    int d = warp;
    const float* hn = g_hn;
    float4 acc = *reinterpret_cast<const float4*>(hn + (size_t)d * 128 + lane * 4);
    float4 acc2 = make_float4(0.f, 0.f, 0.f, 0.f);
    int e = g_start[d], e1 = g_end[d];
    for (; e + 4 <= e1; e += 4) {
        int s0 = g_srcsorted[e],     s1 = g_srcsorted[e + 1];
        int s2 = g_srcsorted[e + 2], s3 = g_srcsorted[e + 3];
        float4 v0 = *reinterpret_cast<const float4*>(hn + (size_t)s0 * 128 + lane * 4);
        float4 v1 = *reinterpret_cast<const float4*>(hn + (size_t)s1 * 128 + lane * 4);
        float4 v2 = *reinterpret_cast<const float4*>(hn + (size_t)s2 * 128 + lane * 4);
        float4 v3 = *reinterpret_cast<const float4*>(hn + (size_t)s3 * 128 + lane * 4);
        acc.x += v0.x; acc.y += v0.y; acc.z += v0.z; acc.w += v0.w;
        acc2.x += v1.x; acc2.y += v1.y; acc2.z += v1.z; acc2.w += v1.w;
        acc.x += v2.x; acc.y += v2.y; acc.z += v2.z; acc.w += v2.w;
        acc2.x += v3.x; acc2.y += v3.y; acc2.z += v3.z; acc2.w += v3.w;
    }
    for (; e < e1; e++) {
        int s = g_srcsorted[e];
        float4 v = *reinterpret_cast<const float4*>(hn + (size_t)s * 128 + lane * 4);
        acc.x += v.x; acc.y += v.y; acc.z += v.z; acc.w += v.w;
    }
    acc.x += acc2.x; acc.y += acc2.y; acc.z += acc2.z; acc.w += acc2.w;
    float dv = g_dinv[d];
    float4 bv = *reinterpret_cast<const float4*>(bias + lane * 4);
    float4 o;
    o.x = to_tf32(fmaxf(fmaf(acc.x, dv, bv.x), 0.f));
    o.y = to_tf32(fmaxf(fmaf(acc.y, dv, bv.y), 0.f));
    o.z = to_tf32(fmaxf(fmaf(acc.z, dv, bv.z), 0.f));
    o.w = to_tf32(fmaxf(fmaf(acc.w, dv, bv.w), 0.f));
    *reinterpret_cast<float4*>(g_x2 + (size_t)d * 128 + lane * 4) = o;
}

// out[d] = dinv[d]*(hn[d] + sum hn[s]) + b2   (F=64, no relu, hn pre-scaled)
__global__ void k_agg64(const float* __restrict__ bias,
                        float* __restrict__ out, int n_nodes) {
    int warp = (blockIdx.x * blockDim.x + threadIdx.x) >> 5;
    int lane = threadIdx.x & 31;
    if (warp >= n_nodes) return;
    int d = warp;
    const float* hn = g_hn;
    float2 acc = *reinterpret_cast<const float2*>(hn + (size_t)d * 64 + lane * 2);
    float2 acc2 = make_float2(0.f, 0.f);
    int e = g_start[d], e1 = g_end[d];
    for (; e + 4 <= e1; e += 4) {
        int s0 = g_srcsorted[e],     s1 = g_srcsorted[e + 1];
        int s2 = g_srcsorted[e + 2], s3 = g_srcsorted[e + 3];
        float2 v0 = *reinterpret_cast<const float2*>(hn + (size_t)s0 * 64 + lane * 2);
        float2 v1 = *reinterpret_cast<const float2*>(hn + (size_t)s1 * 64 + lane * 2);
        float2 v2 = *reinterpret_cast<const float2*>(hn + (size_t)s2 * 64 + lane * 2);
        float2 v3 = *reinterpret_cast<const float2*>(hn + (size_t)s3 * 64 + lane * 2);
        acc.x += v0.x; acc.y += v0.y;
        acc2.x += v1.x; acc2.y += v1.y;
        acc.x += v2.x; acc.y += v2.y;
        acc2.x += v3.x; acc2.y += v3.y;
    }
    for (; e < e1; e++) {
        int s = g_srcsorted[e];
        float2 v = *reinterpret_cast<const float2*>(hn + (size_t)s * 64 + lane * 2);
        acc.x += v.x; acc.y += v.y;
    }
    acc.x += acc2.x; acc.y += acc2.y;
    float dv = g_dinv[d];
    float2 bv = *reinterpret_cast<const float2*>(bias + lane * 2);
    float2 o;
    o.x = fmaf(acc.x, dv, bv.x);
    o.y = fmaf(acc.y, dv, bv.y);
    *reinterpret_cast<float2*>(out + (size_t)d * 64 + lane * 2) = o;
}

// ---------------- launch (single stream — no events, no forks) ----------------
extern "C" void kernel_launch(void* const* d_in, const int* in_sizes, int n_in,
                              void* d_out, int out_size) {
    const float* x  = (const float*)d_in[0];
    const int*   ei = (const int*)d_in[1];     // int32 [2, E]
    const float* W1 = (const float*)d_in[2];
    const float* b1 = (const float*)d_in[3];
    const float* W2 = (const float*)d_in[4];
    const float* b2 = (const float*)d_in[5];
    float* out = (float*)d_out;

    int n_nodes = in_sizes[0] / FIN;       // 100000
    int n_edges = in_sizes[1] / 2;         // 600000

    int nb_edges = (n_edges + 255) / 256;
    int nb_scan  = (n_nodes + 1023) / 1024;
    int nb_gemm  = (n_nodes + TM - 1) / TM;
    int nb_agg   = (n_nodes * 32 + 255) / 256;
    int nb_round = (FIN * FHID + 255) / 256;

    static bool init_done = false;
    if (!init_done) {
        cudaFuncSetAttribute(k_mma_dinv<FHID, 0, 1>,
                             cudaFuncAttributeMaxDynamicSharedMemorySize, SMEM_GEMM(FHID));
        cudaFuncSetAttribute(k_mma_dinv<FOUT, 1, 0>,
                             cudaFuncAttributeMaxDynamicSharedMemorySize, SMEM_GEMM(FOUT));
        init_done = true;
    }

    // ---- prep: round weights + CSR build ----
    k_round<<<nb_round, 256>>>(W1, W2);
    k_hist<<<nb_edges, 256>>>(ei, n_edges, n_nodes);
    k_scan<<<nb_scan, 256>>>(n_nodes);
    k_fill<<<nb_edges, 256>>>(ei, n_edges, n_nodes);

    // ---- layer 1 ----
    k_mma_dinv<FHID, 0, 1><<<nb_gemm, 256, SMEM_GEMM(FHID)>>>(x, n_nodes, FIN);
    k_agg128<<<nb_agg, 256>>>(b1, n_nodes);

    // ---- layer 2 ----
    k_mma_dinv<FOUT, 1, 0><<<nb_gemm, 256, SMEM_GEMM(FOUT)>>>(nullptr, n_nodes, FHID);
    k_agg64<<<nb_agg, 256>>>(b2, out, n_nodes);
}

// round 15
// speedup vs baseline: 1.3791x; 1.0314x over previous
#include <cuda_runtime.h>
#include <cstdint>

// ---------------- problem constants ----------------
#define NMAX 100000
#define EMAX 600000
#define FIN  128
#define FHID 128
#define FOUT 64

// ---------------- scratch (static device globals; zero-initialized at load) ----------------
__device__ __align__(16) float g_hn[(size_t)NMAX * FHID];   // per-layer GEMM out (pre-agg)
__device__ __align__(16) float g_x2[(size_t)NMAX * FHID];   // layer-2 input (tf32-rounded)
__device__ __align__(16) float g_dinv[NMAX];
__device__ __align__(16) float g_w1r[FIN * FHID];           // tf32-rounded W1
__device__ __align__(16) float g_w2r[FHID * FOUT];          // tf32-rounded W2
__device__ int   g_count[NMAX];     // zeroed by k_scan after reading (self-cleaning)
__device__ int   g_start[NMAX];
__device__ int   g_end[NMAX];
__device__ int   g_cursor[NMAX];
__device__ int   g_srcsorted[EMAX];
__device__ int   g_total;           // zeroed by k_fill after scan consumed it

// ---------------- TF32 helpers ----------------
__device__ __forceinline__ float to_tf32(float x) {
    uint32_t u;
    asm("cvt.rna.tf32.f32 %0, %1;" : "=r"(u) : "f"(x));
    return __uint_as_float(u);
}

// ---------------- degree hist + fused weight pre-rounding ----------------
// edge_index is int32, layout [2, E]: src = ei[e], dst = ei[E + e]
__global__ void k_hist(const int* __restrict__ ei,
                       const float* __restrict__ W1, const float* __restrict__ W2,
                       int n_edges, int n_nodes) {
    int e = blockIdx.x * blockDim.x + threadIdx.x;
    if (e < FIN * FHID)  g_w1r[e] = to_tf32(W1[e]);
    if (e < FHID * FOUT) g_w2r[e] = to_tf32(W2[e]);
    if (e < n_edges) {
        int d = ei[n_edges + e];
        if ((unsigned)d < (unsigned)n_nodes) atomicAdd(&g_count[d], 1);
    }
}

// ONE-PASS order-free scan: per-block local prefix + atomic base grab.
// Consumes g_count (re-zeros it for the next replay), writes start/end/cursor/dinv.
__global__ void k_scan(int n) {
    __shared__ int s[256];
    __shared__ int base_sh;
    int t = threadIdx.x;
    int blk = blockIdx.x * 1024;
    int vals[4];
    int tsum = 0;
    #pragma unroll
    for (int k = 0; k < 4; k++) {
        int i = blk + t * 4 + k;
        vals[k] = (i < n) ? g_count[i] : 0;
        tsum += vals[k];
    }
    s[t] = tsum;
    __syncthreads();
    for (int off = 1; off < 256; off <<= 1) {
        int x = (t >= off) ? s[t - off] : 0;
        __syncthreads();
        s[t] += x;
        __syncthreads();
    }
    if (t == 255) base_sh = atomicAdd(&g_total, s[255]);
    __syncthreads();
    int texcl = s[t] - tsum + base_sh;
    int run = 0;
    #pragma unroll
    for (int k = 0; k < 4; k++) {
        int i = blk + t * 4 + k;
        if (i < n) {
            int o = texcl + run;
            g_start[i]  = o;
            g_end[i]    = o + vals[k];
            g_cursor[i] = o;
            g_dinv[i]   = rsqrtf((float)(vals[k] + 1));   // +1 self loop
            g_count[i]  = 0;                              // self-clean for next replay
        }
        run += vals[k];
    }
}

__global__ void k_fill(const int* __restrict__ ei, int n_edges, int n_nodes) {
    int e = blockIdx.x * blockDim.x + threadIdx.x;
    if (e == 0) g_total = 0;        // self-clean (scan already consumed it)
    if (e < n_edges) {
        int srcv = ei[e];
        int d    = ei[n_edges + e];
        if ((unsigned)d < (unsigned)n_nodes && (unsigned)srcv < (unsigned)n_nodes) {
            int p = atomicAdd(&g_cursor[d], 1);
            g_srcsorted[p] = srcv;
        }
    }
}

// ---------------- mma / cp.async helpers ----------------
__device__ __forceinline__ void mma_tf32(float c[4], const float a[4], float b0, float b1) {
    uint32_t const* A = reinterpret_cast<uint32_t const*>(a);
    uint32_t B0 = __float_as_uint(b0), B1 = __float_as_uint(b1);
    asm volatile(
        "mma.sync.aligned.m16n8k8.row.col.f32.tf32.tf32.f32 "
        "{%0,%1,%2,%3}, {%4,%5,%6,%7}, {%8,%9}, {%0,%1,%2,%3};"
        : "+f"(c[0]), "+f"(c[1]), "+f"(c[2]), "+f"(c[3])
        : "r"(A[0]), "r"(A[1]), "r"(A[2]), "r"(A[3]), "r"(B0), "r"(B1));
}

__device__ __forceinline__ void cp_async16(float* smem_ptr, const float* gptr, bool valid) {
    uint32_t sa = (uint32_t)__cvta_generic_to_shared(smem_ptr);
    int sz = valid ? 16 : 0;
    asm volatile("cp.async.cg.shared.global [%0], [%1], 16, %2;"
                 :: "r"(sa), "l"(gptr), "r"(sz));
}
#define CP_COMMIT() asm volatile("cp.async.commit_group;" ::: "memory")
#define CP_WAIT(N)  asm volatile("cp.async.wait_group %0;" :: "n"(N) : "memory")

// ---------------- cp.async double-buffered TF32 GEMM with fused dinv epilogue ----------------
// g_hn[m,n] = g_dinv[m] * sum_k A[m,k]*B[k,n]
// B from DEVICE-GLOBAL pre-rounded weights: BN==128 -> g_w1r, BN==64 -> g_w2r.
// ACVT=1: round A fragments in-loop (layer-1 raw x); ACVT=0: A already tf32 (g_x2).
// TM=64 rows/CTA, 8 warps = 2(M) x 4(N), 3 CTAs/SM.
#define KC 32
#define TM 64
#define AP 36
#define ASTRIDE (TM * AP)

template <int BN, int SRC, int ACVT>
__global__ void __launch_bounds__(256, 3)
k_mma_dinv(const float* __restrict__ Aext, int M, int K) {
    const float* __restrict__ A  = (SRC == 0) ? Aext : g_x2;
    const float* __restrict__ Bg = (BN == FHID) ? g_w1r : g_w2r;
    const int BPITCH  = BN + 8;
    const int BSTRIDE = KC * BPITCH;
    const int BTPR    = BN / 4;
    const int BKSTEP  = 256 / BTPR;
    const int NBB     = KC / BKSTEP;

    extern __shared__ float sm[];
    float* As0 = sm;
    float* Bs0 = sm + 2 * ASTRIDE;

    int tid  = threadIdx.x;
    int warp = tid >> 5, lane = tid & 31;
    int wm = warp & 1, wn = warp >> 1;  // 2(M) x 4(N)
    const int WNT = BN / 4;
    const int NF  = WNT / 8;
    int g  = lane >> 2, tg = lane & 3;
    int row0 = blockIdx.x * TM;

    int ar = tid >> 3, ac = (tid & 7) * 4;
    int bkr = tid / BTPR, bbc = (tid % BTPR) * 4;

    auto issue = [&](int kc) {
        float* As = As0 + (kc & 1) * ASTRIDE;
        float* Bs = Bs0 + (kc & 1) * BSTRIDE;
        int k0 = kc * KC;
        #pragma unroll
        for (int i = 0; i < 2; i++) {
            int rr = ar + i * 32;
            cp_async16(&As[rr * AP + ac],
                       A + (size_t)(row0 + rr) * K + k0 + ac,
                       row0 + rr < M);
        }
        #pragma unroll
        for (int i = 0; i < NBB; i++) {
            int kk = bkr + i * BKSTEP;
            cp_async16(&Bs[kk * BPITCH + bbc],
                       Bg + (size_t)(k0 + kk) * BN + bbc, true);
        }
    };

    float acc[2][NF][4];
    #pragma unroll
    for (int i = 0; i < 2; i++)
        #pragma unroll
        for (int j = 0; j < NF; j++)
            #pragma unroll
            for (int q = 0; q < 4; q++) acc[i][j][q] = 0.0f;

    issue(0); CP_COMMIT();

    const int NCHUNK = K / KC;
    for (int kc = 0; kc < NCHUNK; kc++) {
        if (kc + 1 < NCHUNK) { issue(kc + 1); CP_COMMIT(); CP_WAIT(1); }
        else                 { CP_WAIT(0); }
        __syncthreads();

        float* As = As0 + (kc & 1) * ASTRIDE;
        float* Bs = Bs0 + (kc & 1) * BSTRIDE;

        #pragma unroll
        for (int ks = 0; ks < KC; ks += 8) {
            float a[2][4];
            #pragma unroll
            for (int mf = 0; mf < 2; mf++) {
                int arr = wm * 32 + mf * 16;
                a[mf][0] = As[(arr + g)     * AP + ks + tg];
                a[mf][1] = As[(arr + g + 8) * AP + ks + tg];
                a[mf][2] = As[(arr + g)     * AP + ks + tg + 4];
                a[mf][3] = As[(arr + g + 8) * AP + ks + tg + 4];
                if (ACVT) {
                    a[mf][0] = to_tf32(a[mf][0]);
                    a[mf][1] = to_tf32(a[mf][1]);
                    a[mf][2] = to_tf32(a[mf][2]);
                    a[mf][3] = to_tf32(a[mf][3]);
                }
            }
            #pragma unroll
            for (int nf = 0; nf < NF; nf++) {
                int bn0 = wn * WNT + nf * 8;
                float b0 = Bs[(ks + tg)     * BPITCH + bn0 + g];
                float b1 = Bs[(ks + tg + 4) * BPITCH + bn0 + g];
                #pragma unroll
                for (int mf = 0; mf < 2; mf++)
                    mma_tf32(acc[mf][nf], a[mf], b0, b1);
            }
        }
        __syncthreads();
    }

    #pragma unroll
    for (int mf = 0; mf < 2; mf++) {
        int r0 = row0 + wm * 32 + mf * 16 + g;
        int r1 = r0 + 8;
        float d0 = (r0 < M) ? g_dinv[r0] : 0.f;
        float d1 = (r1 < M) ? g_dinv[r1] : 0.f;
        #pragma unroll
        for (int nf = 0; nf < NF; nf++) {
            int cc = wn * WNT + nf * 8 + tg * 2;
            if (r0 < M) {
                g_hn[(size_t)r0 * BN + cc]     = acc[mf][nf][0] * d0;
                g_hn[(size_t)r0 * BN + cc + 1] = acc[mf][nf][1] * d0;
            }
            if (r1 < M) {
                g_hn[(size_t)r1 * BN + cc]     = acc[mf][nf][2] * d1;
                g_hn[(size_t)r1 * BN + cc + 1] = acc[mf][nf][3] * d1;
            }
        }
    }
}

#define SMEM_GEMM(BN) ((2 * ASTRIDE + 2 * KC * ((BN) + 8)) * 4)

// ---------------- aggregation: one warp per node, MLP-4 gathers ----------------
// x2[d] = tf32(relu( dinv[d]*(hn[d] + sum hn[s]) + b1 ))   (F=128, hn pre-scaled)
__global__ void k_agg128(const float* __restrict__ bias, int n_nodes) {
    int warp = (blockIdx.x * blockDim.x + threadIdx.x) >> 5;
    int lane = threadIdx.x & 31;
    if (warp >= n_nodes) return;
    int d = warp;
    const float* hn = g_hn;
    float4 acc = *reinterpret_cast<const float4*>(hn + (size_t)d * 128 + lane * 4);
    float4 acc2 = make_float4(0.f, 0.f, 0.f, 0.f);
    int e = g_start[d], e1 = g_end[d];
    for (; e + 4 <= e1; e += 4) {
        int s0 = g_srcsorted[e],     s1 = g_srcsorted[e + 1];
        int s2 = g_srcsorted[e + 2], s3 = g_srcsorted[e + 3];
        float4 v0 = *reinterpret_cast<const float4*>(hn + (size_t)s0 * 128 + lane * 4);
        float4 v1 = *reinterpret_cast<const float4*>(hn + (size_t)s1 * 128 + lane * 4);
        float4 v2 = *reinterpret_cast<const float4*>(hn + (size_t)s2 * 128 + lane * 4);
        float4 v3 = *reinterpret_cast<const float4*>(hn + (size_t)s3 * 128 + lane * 4);
        acc.x += v0.x; acc.y += v0.y; acc.z += v0.z; acc.w += v0.w;
        acc2.x += v1.x; acc2.y += v1.y; acc2.z += v1.z; acc2.w += v1.w;
        acc.x += v2.x; acc.y += v2.y; acc.z += v2.z; acc.w += v2.w;
        acc2.x += v3.x; acc2.y += v3.y; acc2.z += v3.z; acc2.w += v3.w;
    }
    for (; e < e1; e++) {
        int s = g_srcsorted[e];
        float4 v = *reinterpret_cast<const float4*>(hn + (size_t)s * 128 + lane * 4);
        acc.x += v.x; acc.y += v.y; acc.z += v.z; acc.w += v.w;
    }
    acc.x += acc2.x; acc.y += acc2.y; acc.z += acc2.z; acc.w += acc2.w;
    float dv = g_dinv[d];
    float4 bv = *reinterpret_cast<const float4*>(bias + lane * 4);
    float4 o;
    o.x = to_tf32(fmaxf(fmaf(acc.x, dv, bv.x), 0.f));
    o.y = to_tf32(fmaxf(fmaf(acc.y, dv, bv.y), 0.f));
    o.z = to_tf32(fmaxf(fmaf(acc.z, dv, bv.z), 0.f));
    o.w = to_tf32(fmaxf(fmaf(acc.w, dv, bv.w), 0.f));
    *reinterpret_cast<float4*>(g_x2 + (size_t)d * 128 + lane * 4) = o;
}

// out[d] = dinv[d]*(hn[d] + sum hn[s]) + b2   (F=64, no relu, hn pre-scaled)
__global__ void k_agg64(const float* __restrict__ bias,
                        float* __restrict__ out, int n_nodes) {
    int warp = (blockIdx.x * blockDim.x + threadIdx.x) >> 5;
    int lane = threadIdx.x & 31;
    if (warp >= n_nodes) return;
    int d = warp;
    const float* hn = g_hn;
    float2 acc = *reinterpret_cast<const float2*>(hn + (size_t)d * 64 + lane * 2);
    float2 acc2 = make_float2(0.f, 0.f);
    int e = g_start[d], e1 = g_end[d];
    for (; e + 4 <= e1; e += 4) {
        int s0 = g_srcsorted[e],     s1 = g_srcsorted[e + 1];
        int s2 = g_srcsorted[e + 2], s3 = g_srcsorted[e + 3];
        float2 v0 = *reinterpret_cast<const float2*>(hn + (size_t)s0 * 64 + lane * 2);
        float2 v1 = *reinterpret_cast<const float2*>(hn + (size_t)s1 * 64 + lane * 2);
        float2 v2 = *reinterpret_cast<const float2*>(hn + (size_t)s2 * 64 + lane * 2);
        float2 v3 = *reinterpret_cast<const float2*>(hn + (size_t)s3 * 64 + lane * 2);
        acc.x += v0.x; acc.y += v0.y;
        acc2.x += v1.x; acc2.y += v1.y;
        acc.x += v2.x; acc.y += v2.y;
        acc2.x += v3.x; acc2.y += v3.y;
    }
    for (; e < e1; e++) {
        int s = g_srcsorted[e];
        float2 v = *reinterpret_cast<const float2*>(hn + (size_t)s * 64 + lane * 2);
        acc.x += v.x; acc.y += v.y;
    }
    acc.x += acc2.x; acc.y += acc2.y;
    float dv = g_dinv[d];
    float2 bv = *reinterpret_cast<const float2*>(bias + lane * 2);
    float2 o;
    o.x = fmaf(acc.x, dv, bv.x);
    o.y = fmaf(acc.y, dv, bv.y);
    *reinterpret_cast<float2*>(out + (size_t)d * 64 + lane * 2) = o;
}

// ---------------- launch (narrow fork: fill overlaps GEMM1, round-11 pattern) ----------------
extern "C" void kernel_launch(void* const* d_in, const int* in_sizes, int n_in,
                              void* d_out, int out_size) {
    const float* x  = (const float*)d_in[0];
    const int*   ei = (const int*)d_in[1];     // int32 [2, E]
    const float* W1 = (const float*)d_in[2];
    const float* b1 = (const float*)d_in[3];
    const float* W2 = (const float*)d_in[4];
    const float* b2 = (const float*)d_in[5];
    float* out = (float*)d_out;

    int n_nodes = in_sizes[0] / FIN;       // 100000
    int n_edges = in_sizes[1] / 2;         // 600000

    int nb_edges = (n_edges + 255) / 256;
    int nb_scan  = (n_nodes + 1023) / 1024;
    int nb_gemm  = (n_nodes + TM - 1) / TM;
    int nb_agg   = (n_nodes * 32 + 255) / 256;

    // one-time stream/event/attr setup (first call is the uncaptured correctness run)
    static cudaStream_t s2 = nullptr;
    static cudaEvent_t evFork = nullptr, evJoin = nullptr;
    if (!s2) {
        cudaStreamCreateWithFlags(&s2, cudaStreamNonBlocking);
        cudaEventCreateWithFlags(&evFork, cudaEventDisableTiming);
        cudaEventCreateWithFlags(&evJoin, cudaEventDisableTiming);
        cudaFuncSetAttribute(k_mma_dinv<FHID, 0, 1>,
                             cudaFuncAttributeMaxDynamicSharedMemorySize, SMEM_GEMM(FHID));
        cudaFuncSetAttribute(k_mma_dinv<FOUT, 1, 0>,
                             cudaFuncAttributeMaxDynamicSharedMemorySize, SMEM_GEMM(FOUT));
    }

    // ---- CSR: hist (+ fused weight rounding) -> scan, main stream ----
    k_hist<<<nb_edges, 256>>>(ei, W1, W2, n_edges, n_nodes);
    k_scan<<<nb_scan, 256>>>(n_nodes);

    // ---- narrow fork: fill (s2) overlaps GEMM1 (main) ----
    cudaEventRecord(evFork, 0);
    cudaStreamWaitEvent(s2, evFork, 0);
    k_fill<<<nb_edges, 256, 0, s2>>>(ei, n_edges, n_nodes);
    cudaEventRecord(evJoin, s2);

    k_mma_dinv<FHID, 0, 1><<<nb_gemm, 256, SMEM_GEMM(FHID)>>>(x, n_nodes, FIN);

    cudaStreamWaitEvent(0, evJoin, 0);   // join: adjacency ready

    // ---- layer 1 aggregation ----
    k_agg128<<<nb_agg, 256>>>(b1, n_nodes);

    // ---- layer 2 ----
    k_mma_dinv<FOUT, 1, 0><<<nb_gemm, 256, SMEM_GEMM(FOUT)>>>(nullptr, n_nodes, FHID);
    k_agg64<<<nb_agg, 256>>>(b2, out, n_nodes);
}

// round 16
// speedup vs baseline: 1.4281x; 1.0355x over previous
#include <cuda_runtime.h>
#include <cuda_fp16.h>
#include <cstdint>

// ---------------- problem constants ----------------
#define NMAX 100000
#define EMAX 600000
#define FIN  128
#define FHID 128
#define FOUT 64

// ---------------- scratch (static device globals; zero-initialized at load) ----------------
__device__ __align__(16) __half g_hnh[(size_t)NMAX * FHID]; // per-layer GEMM out (fp16, pre-agg)
__device__ __align__(16) float g_x2[(size_t)NMAX * FHID];   // layer-2 input (tf32-rounded, fp32)
__device__ __align__(16) float g_dinv[NMAX];
__device__ __align__(16) float g_w1r[FIN * FHID];           // tf32-rounded W1
__device__ __align__(16) float g_w2r[FHID * FOUT];          // tf32-rounded W2
__device__ int   g_count[NMAX];     // zeroed by k_scan after reading (self-cleaning)
__device__ int   g_start[NMAX];
__device__ int   g_end[NMAX];
__device__ int   g_cursor[NMAX];
__device__ int   g_srcsorted[EMAX];
__device__ int   g_total;           // zeroed by k_fill after scan consumed it

// ---------------- TF32 helpers ----------------
__device__ __forceinline__ float to_tf32(float x) {
    uint32_t u;
    asm("cvt.rna.tf32.f32 %0, %1;" : "=r"(u) : "f"(x));
    return __uint_as_float(u);
}

// ---------------- degree hist + fused weight pre-rounding ----------------
// edge_index is int32, layout [2, E]: src = ei[e], dst = ei[E + e]
__global__ void k_hist(const int* __restrict__ ei,
                       const float* __restrict__ W1, const float* __restrict__ W2,
                       int n_edges, int n_nodes) {
    int e = blockIdx.x * blockDim.x + threadIdx.x;
    if (e < FIN * FHID)  g_w1r[e] = to_tf32(W1[e]);
    if (e < FHID * FOUT) g_w2r[e] = to_tf32(W2[e]);
    if (e < n_edges) {
        int d = ei[n_edges + e];
        if ((unsigned)d < (unsigned)n_nodes) atomicAdd(&g_count[d], 1);
    }
}

// ONE-PASS order-free scan: per-block local prefix + atomic base grab.
// Consumes g_count (re-zeros it for the next replay), writes start/end/cursor/dinv.
__global__ void k_scan(int n) {
    __shared__ int s[256];
    __shared__ int base_sh;
    int t = threadIdx.x;
    int blk = blockIdx.x * 1024;
    int vals[4];
    int tsum = 0;
    #pragma unroll
    for (int k = 0; k < 4; k++) {
        int i = blk + t * 4 + k;
        vals[k] = (i < n) ? g_count[i] : 0;
        tsum += vals[k];
    }
    s[t] = tsum;
    __syncthreads();
    for (int off = 1; off < 256; off <<= 1) {
        int x = (t >= off) ? s[t - off] : 0;
        __syncthreads();
        s[t] += x;
        __syncthreads();
    }
    if (t == 255) base_sh = atomicAdd(&g_total, s[255]);
    __syncthreads();
    int texcl = s[t] - tsum + base_sh;
    int run = 0;
    #pragma unroll
    for (int k = 0; k < 4; k++) {
        int i = blk + t * 4 + k;
        if (i < n) {
            int o = texcl + run;
            g_start[i]  = o;
            g_end[i]    = o + vals[k];
            g_cursor[i] = o;
            g_dinv[i]   = rsqrtf((float)(vals[k] + 1));   // +1 self loop
            g_count[i]  = 0;                              // self-clean for next replay
        }
        run += vals[k];
    }
}

__global__ void k_fill(const int* __restrict__ ei, int n_edges, int n_nodes) {
    int e = blockIdx.x * blockDim.x + threadIdx.x;
    if (e == 0) g_total = 0;        // self-clean (scan already consumed it)
    if (e < n_edges) {
        int srcv = ei[e];
        int d    = ei[n_edges + e];
        if ((unsigned)d < (unsigned)n_nodes && (unsigned)srcv < (unsigned)n_nodes) {
            int p = atomicAdd(&g_cursor[d], 1);
            g_srcsorted[p] = srcv;
        }
    }
}

// ---------------- mma / cp.async helpers ----------------
__device__ __forceinline__ void mma_tf32(float c[4], const float a[4], float b0, float b1) {
    uint32_t const* A = reinterpret_cast<uint32_t const*>(a);
    uint32_t B0 = __float_as_uint(b0), B1 = __float_as_uint(b1);
    asm volatile(
        "mma.sync.aligned.m16n8k8.row.col.f32.tf32.tf32.f32 "
        "{%0,%1,%2,%3}, {%4,%5,%6,%7}, {%8,%9}, {%0,%1,%2,%3};"
        : "+f"(c[0]), "+f"(c[1]), "+f"(c[2]), "+f"(c[3])
        : "r"(A[0]), "r"(A[1]), "r"(A[2]), "r"(A[3]), "r"(B0), "r"(B1));
}

__device__ __forceinline__ void cp_async16(float* smem_ptr, const float* gptr, bool valid) {
    uint32_t sa = (uint32_t)__cvta_generic_to_shared(smem_ptr);
    int sz = valid ? 16 : 0;
    asm volatile("cp.async.cg.shared.global [%0], [%1], 16, %2;"
                 :: "r"(sa), "l"(gptr), "r"(sz));
}
#define CP_COMMIT() asm volatile("cp.async.commit_group;" ::: "memory")
#define CP_WAIT(N)  asm volatile("cp.async.wait_group %0;" :: "n"(N) : "memory")

// ---------------- cp.async double-buffered TF32 GEMM, fp16 output, fused dinv ----------------
// g_hnh[m,n] = (half) g_dinv[m] * sum_k A[m,k]*B[k,n]
// B from pre-rounded device weights: BN==128 -> g_w1r, BN==64 -> g_w2r.
// ACVT=1: round A fragments in-loop (layer-1 raw x); ACVT=0: A already tf32 (g_x2).
// TM=64 rows/CTA, 8 warps = 2(M) x 4(N), 3 CTAs/SM.
#define KC 32
#define TM 64
#define AP 36
#define ASTRIDE (TM * AP)

template <int BN, int SRC, int ACVT>
__global__ void __launch_bounds__(256, 3)
k_mma_dinv(const float* __restrict__ Aext, int M, int K) {
    const float* __restrict__ A  = (SRC == 0) ? Aext : g_x2;
    const float* __restrict__ Bg = (BN == FHID) ? g_w1r : g_w2r;
    const int BPITCH  = BN + 8;
    const int BSTRIDE = KC * BPITCH;
    const int BTPR    = BN / 4;
    const int BKSTEP  = 256 / BTPR;
    const int NBB     = KC / BKSTEP;

    extern __shared__ float sm[];
    float* As0 = sm;
    float* Bs0 = sm + 2 * ASTRIDE;

    int tid  = threadIdx.x;
    int warp = tid >> 5, lane = tid & 31;
    int wm = warp & 1, wn = warp >> 1;  // 2(M) x 4(N)
    const int WNT = BN / 4;
    const int NF  = WNT / 8;
    int g  = lane >> 2, tg = lane & 3;
    int row0 = blockIdx.x * TM;

    int ar = tid >> 3, ac = (tid & 7) * 4;
    int bkr = tid / BTPR, bbc = (tid % BTPR) * 4;

    auto issue = [&](int kc) {
        float* As = As0 + (kc & 1) * ASTRIDE;
        float* Bs = Bs0 + (kc & 1) * BSTRIDE;
        int k0 = kc * KC;
        #pragma unroll
        for (int i = 0; i < 2; i++) {
            int rr = ar + i * 32;
            cp_async16(&As[rr * AP + ac],
                       A + (size_t)(row0 + rr) * K + k0 + ac,
                       row0 + rr < M);
        }
        #pragma unroll
        for (int i = 0; i < NBB; i++) {
            int kk = bkr + i * BKSTEP;
            cp_async16(&Bs[kk * BPITCH + bbc],
                       Bg + (size_t)(k0 + kk) * BN + bbc, true);
        }
    };

    float acc[2][NF][4];
    #pragma unroll
    for (int i = 0; i < 2; i++)
        #pragma unroll
        for (int j = 0; j < NF; j++)
            #pragma unroll
            for (int q = 0; q < 4; q++) acc[i][j][q] = 0.0f;

    issue(0); CP_COMMIT();

    const int NCHUNK = K / KC;
    for (int kc = 0; kc < NCHUNK; kc++) {
        if (kc + 1 < NCHUNK) { issue(kc + 1); CP_COMMIT(); CP_WAIT(1); }
        else                 { CP_WAIT(0); }
        __syncthreads();

        float* As = As0 + (kc & 1) * ASTRIDE;
        float* Bs = Bs0 + (kc & 1) * BSTRIDE;

        #pragma unroll
        for (int ks = 0; ks < KC; ks += 8) {
            float a[2][4];
            #pragma unroll
            for (int mf = 0; mf < 2; mf++) {
                int arr = wm * 32 + mf * 16;
                a[mf][0] = As[(arr + g)     * AP + ks + tg];
                a[mf][1] = As[(arr + g + 8) * AP + ks + tg];
                a[mf][2] = As[(arr + g)     * AP + ks + tg + 4];
                a[mf][3] = As[(arr + g + 8) * AP + ks + tg + 4];
                if (ACVT) {
                    a[mf][0] = to_tf32(a[mf][0]);
                    a[mf][1] = to_tf32(a[mf][1]);
                    a[mf][2] = to_tf32(a[mf][2]);
                    a[mf][3] = to_tf32(a[mf][3]);
                }
            }
            #pragma unroll
            for (int nf = 0; nf < NF; nf++) {
                int bn0 = wn * WNT + nf * 8;
                float b0 = Bs[(ks + tg)     * BPITCH + bn0 + g];
                float b1 = Bs[(ks + tg + 4) * BPITCH + bn0 + g];
                #pragma unroll
                for (int mf = 0; mf < 2; mf++)
                    mma_tf32(acc[mf][nf], a[mf], b0, b1);
            }
        }
        __syncthreads();
    }

    // epilogue: scale by dinv, convert to fp16, store pairs (cc even -> 4B aligned)
    #pragma unroll
    for (int mf = 0; mf < 2; mf++) {
        int r0 = row0 + wm * 32 + mf * 16 + g;
        int r1 = r0 + 8;
        float d0 = (r0 < M) ? g_dinv[r0] : 0.f;
        float d1 = (r1 < M) ? g_dinv[r1] : 0.f;
        #pragma unroll
        for (int nf = 0; nf < NF; nf++) {
            int cc = wn * WNT + nf * 8 + tg * 2;
            if (r0 < M) {
                __half2 h = __floats2half2_rn(acc[mf][nf][0] * d0, acc[mf][nf][1] * d0);
                *reinterpret_cast<__half2*>(g_hnh + (size_t)r0 * BN + cc) = h;
            }
            if (r1 < M) {
                __half2 h = __floats2half2_rn(acc[mf][nf][2] * d1, acc[mf][nf][3] * d1);
                *reinterpret_cast<__half2*>(g_hnh + (size_t)r1 * BN + cc) = h;
            }
        }
    }
}

#define SMEM_GEMM(BN) ((2 * ASTRIDE + 2 * KC * ((BN) + 8)) * 4)

// ---------------- fp16 row-load helpers ----------------
__device__ __forceinline__ float4 ld_hn4(const __half* base, size_t row, int pitch, int lane) {
    // 4 consecutive halves at feature offset lane*4 (8B aligned)
    uint2 raw = *reinterpret_cast<const uint2*>(base + row * pitch + lane * 4);
    __half2 h0 = *reinterpret_cast<const __half2*>(&raw.x);
    __half2 h1 = *reinterpret_cast<const __half2*>(&raw.y);
    float2 f0 = __half22float2(h0);
    float2 f1 = __half22float2(h1);
    return make_float4(f0.x, f0.y, f1.x, f1.y);
}

__device__ __forceinline__ float2 ld_hn2(const __half* base, size_t row, int pitch, int lane) {
    uint32_t raw = *reinterpret_cast<const uint32_t*>(base + row * pitch + lane * 2);
    __half2 h = *reinterpret_cast<const __half2*>(&raw);
    return __half22float2(h);
}

// ---------------- aggregation: one warp per node, MLP-4 fp16 gathers ----------------
// x2[d] = tf32(relu( dinv[d]*(hn[d] + sum hn[s]) + b1 ))   (F=128, hn fp16 pre-scaled)
__global__ void k_agg128(const float* __restrict__ bias, int n_nodes) {
    int warp = (blockIdx.x * blockDim.x + threadIdx.x) >> 5;
    int lane = threadIdx.x & 31;
    if (warp >= n_nodes) return;
    int d = warp;
    const __half* hn = g_hnh;
    float4 acc = ld_hn4(hn, (size_t)d, 128, lane);
    float4 acc2 = make_float4(0.f, 0.f, 0.f, 0.f);
    int e = g_start[d], e1 = g_end[d];
    for (; e + 4 <= e1; e += 4) {
        int s0 = g_srcsorted[e],     s1 = g_srcsorted[e + 1];
        int s2 = g_srcsorted[e + 2], s3 = g_srcsorted[e + 3];
        float4 v0 = ld_hn4(hn, (size_t)s0, 128, lane);
        float4 v1 = ld_hn4(hn, (size_t)s1, 128, lane);
        float4 v2 = ld_hn4(hn, (size_t)s2, 128, lane);
        float4 v3 = ld_hn4(hn, (size_t)s3, 128, lane);
        acc.x += v0.x; acc.y += v0.y; acc.z += v0.z; acc.w += v0.w;
        acc2.x += v1.x; acc2.y += v1.y; acc2.z += v1.z; acc2.w += v1.w;
        acc.x += v2.x; acc.y += v2.y; acc.z += v2.z; acc.w += v2.w;
        acc2.x += v3.x; acc2.y += v3.y; acc2.z += v3.z; acc2.w += v3.w;
    }
    for (; e < e1; e++) {
        int s = g_srcsorted[e];
        float4 v = ld_hn4(hn, (size_t)s, 128, lane);
        acc.x += v.x; acc.y += v.y; acc.z += v.z; acc.w += v.w;
    }
    acc.x += acc2.x; acc.y += acc2.y; acc.z += acc2.z; acc.w += acc2.w;
    float dv = g_dinv[d];
    float4 bv = *reinterpret_cast<const float4*>(bias + lane * 4);
    float4 o;
    o.x = to_tf32(fmaxf(fmaf(acc.x, dv, bv.x), 0.f));
    o.y = to_tf32(fmaxf(fmaf(acc.y, dv, bv.y), 0.f));
    o.z = to_tf32(fmaxf(fmaf(acc.z, dv, bv.z), 0.f));
    o.w = to_tf32(fmaxf(fmaf(acc.w, dv, bv.w), 0.f));
    *reinterpret_cast<float4*>(g_x2 + (size_t)d * 128 + lane * 4) = o;
}

// out[d] = dinv[d]*(hn2[d] + sum hn2[s]) + b2   (F=64, no relu, hn2 fp16 pre-scaled)
__global__ void k_agg64(const float* __restrict__ bias,
                        float* __restrict__ out, int n_nodes) {
    int warp = (blockIdx.x * blockDim.x + threadIdx.x) >> 5;
    int lane = threadIdx.x & 31;
    if (warp >= n_nodes) return;
    int d = warp;
    const __half* hn = g_hnh;
    float2 acc = ld_hn2(hn, (size_t)d, 64, lane);
    float2 acc2 = make_float2(0.f, 0.f);
    int e = g_start[d], e1 = g_end[d];
    for (; e + 4 <= e1; e += 4) {
        int s0 = g_srcsorted[e],     s1 = g_srcsorted[e + 1];
        int s2 = g_srcsorted[e + 2], s3 = g_srcsorted[e + 3];
        float2 v0 = ld_hn2(hn, (size_t)s0, 64, lane);
        float2 v1 = ld_hn2(hn, (size_t)s1, 64, lane);
        float2 v2 = ld_hn2(hn, (size_t)s2, 64, lane);
        float2 v3 = ld_hn2(hn, (size_t)s3, 64, lane);
        acc.x += v0.x; acc.y += v0.y;
        acc2.x += v1.x; acc2.y += v1.y;
        acc.x += v2.x; acc.y += v2.y;
        acc2.x += v3.x; acc2.y += v3.y;
    }
    for (; e < e1; e++) {
        int s = g_srcsorted[e];
        float2 v = ld_hn2(hn, (size_t)s, 64, lane);
        acc.x += v.x; acc.y += v.y;
    }
    acc.x += acc2.x; acc.y += acc2.y;
    float dv = g_dinv[d];
    float2 bv = *reinterpret_cast<const float2*>(bias + lane * 2);
    float2 o;
    o.x = fmaf(acc.x, dv, bv.x);
    o.y = fmaf(acc.y, dv, bv.y);
    *reinterpret_cast<float2*>(out + (size_t)d * 64 + lane * 2) = o;
}

// ---------------- launch (narrow fork: fill overlaps GEMM1) ----------------
extern "C" void kernel_launch(void* const* d_in, const int* in_sizes, int n_in,
                              void* d_out, int out_size) {
    const float* x  = (const float*)d_in[0];
    const int*   ei = (const int*)d_in[1];     // int32 [2, E]
    const float* W1 = (const float*)d_in[2];
    const float* b1 = (const float*)d_in[3];
    const float* W2 = (const float*)d_in[4];
    const float* b2 = (const float*)d_in[5];
    float* out = (float*)d_out;

    int n_nodes = in_sizes[0] / FIN;       // 100000
    int n_edges = in_sizes[1] / 2;         // 600000

    int nb_edges = (n_edges + 255) / 256;
    int nb_scan  = (n_nodes + 1023) / 1024;
    int nb_gemm  = (n_nodes + TM - 1) / TM;
    int nb_agg   = (n_nodes * 32 + 255) / 256;

    // one-time stream/event/attr setup (first call is the uncaptured correctness run)
    static cudaStream_t s2 = nullptr;
    static cudaEvent_t evFork = nullptr, evJoin = nullptr;
    if (!s2) {
        cudaStreamCreateWithFlags(&s2, cudaStreamNonBlocking);
        cudaEventCreateWithFlags(&evFork, cudaEventDisableTiming);
        cudaEventCreateWithFlags(&evJoin, cudaEventDisableTiming);
        cudaFuncSetAttribute(k_mma_dinv<FHID, 0, 1>,
                             cudaFuncAttributeMaxDynamicSharedMemorySize, SMEM_GEMM(FHID));
        cudaFuncSetAttribute(k_mma_dinv<FOUT, 1, 0>,
                             cudaFuncAttributeMaxDynamicSharedMemorySize, SMEM_GEMM(FOUT));
    }

    // ---- CSR: hist (+ fused weight rounding) -> scan, main stream ----
    k_hist<<<nb_edges, 256>>>(ei, W1, W2, n_edges, n_nodes);
    k_scan<<<nb_scan, 256>>>(n_nodes);

    // ---- narrow fork: fill (s2) overlaps GEMM1 (main) ----
    cudaEventRecord(evFork, 0);
    cudaStreamWaitEvent(s2, evFork, 0);
    k_fill<<<nb_edges, 256, 0, s2>>>(ei, n_edges, n_nodes);
    cudaEventRecord(evJoin, s2);

    k_mma_dinv<FHID, 0, 1><<<nb_gemm, 256, SMEM_GEMM(FHID)>>>(x, n_nodes, FIN);

    cudaStreamWaitEvent(0, evJoin, 0);   // join: adjacency ready

    // ---- layer 1 aggregation ----
    k_agg128<<<nb_agg, 256>>>(b1, n_nodes);

    // ---- layer 2 ----
    k_mma_dinv<FOUT, 1, 0><<<nb_gemm, 256, SMEM_GEMM(FOUT)>>>(nullptr, n_nodes, FHID);
    k_agg64<<<nb_agg, 256>>>(b2, out, n_nodes);
}

// round 17
// speedup vs baseline: 1.4814x; 1.0374x over previous
#include <cuda_runtime.h>
#include <cuda_fp16.h>
#include <cstdint>

// ---------------- problem constants ----------------
#define NMAX 100000
#define EMAX 600000
#define FIN  128
#define FHID 128
#define FOUT 64

// ---------------- scratch (static device globals; zero-initialized at load) ----------------
__device__ __align__(16) __half g_hnh[(size_t)NMAX * FHID]; // per-layer GEMM out (fp16, pre-agg)
__device__ __align__(16) __half g_x2h[(size_t)NMAX * FHID]; // layer-2 input (fp16)
__device__ __align__(16) float  g_dinv[NMAX];
__device__ __align__(16) __half g_w1h[FIN * FHID];          // fp16 W1, TRANSPOSED [n][k]
__device__ __align__(16) __half g_w2h[FHID * FOUT];         // fp16 W2, TRANSPOSED [n][k]
__device__ int   g_count[NMAX];     // zeroed by k_scan after reading (self-cleaning)
__device__ int   g_start[NMAX];
__device__ int   g_end[NMAX];
__device__ int   g_cursor[NMAX];
__device__ int   g_srcsorted[EMAX];
__device__ int   g_total;           // zeroed by k_fill after scan consumed it

// ---------------- degree hist + fused weight convert/transpose ----------------
// edge_index is int32, layout [2, E]: src = ei[e], dst = ei[E + e]
// W1 [FIN][FHID] -> g_w1h[n*FIN + k]; W2 [FHID][FOUT] -> g_w2h[n*FHID + k]
__global__ void k_hist(const int* __restrict__ ei,
                       const float* __restrict__ W1, const float* __restrict__ W2,
                       int n_edges, int n_nodes) {
    int e = blockIdx.x * blockDim.x + threadIdx.x;
    if (e < FIN * FHID) {
        int k = e >> 7, n = e & 127;           // e = k*FHID + n
        g_w1h[n * FIN + k] = __float2half(W1[e]);
    }
    if (e < FHID * FOUT) {
        int k = e >> 6, n = e & 63;            // e = k*FOUT + n
        g_w2h[n * FHID + k] = __float2half(W2[e]);
    }
    if (e < n_edges) {
        int d = ei[n_edges + e];
        if ((unsigned)d < (unsigned)n_nodes) atomicAdd(&g_count[d], 1);
    }
}

// ONE-PASS order-free scan: per-block local prefix + atomic base grab.
// Consumes g_count (re-zeros it for the next replay), writes start/end/cursor/dinv.
__global__ void k_scan(int n) {
    __shared__ int s[256];
    __shared__ int base_sh;
    int t = threadIdx.x;
    int blk = blockIdx.x * 1024;
    int vals[4];
    int tsum = 0;
    #pragma unroll
    for (int k = 0; k < 4; k++) {
        int i = blk + t * 4 + k;
        vals[k] = (i < n) ? g_count[i] : 0;
        tsum += vals[k];
    }
    s[t] = tsum;
    __syncthreads();
    for (int off = 1; off < 256; off <<= 1) {
        int x = (t >= off) ? s[t - off] : 0;
        __syncthreads();
        s[t] += x;
        __syncthreads();
    }
    if (t == 255) base_sh = atomicAdd(&g_total, s[255]);
    __syncthreads();
    int texcl = s[t] - tsum + base_sh;
    int run = 0;
    #pragma unroll
    for (int k = 0; k < 4; k++) {
        int i = blk + t * 4 + k;
        if (i < n) {
            int o = texcl + run;
            g_start[i]  = o;
            g_end[i]    = o + vals[k];
            g_cursor[i] = o;
            g_dinv[i]   = rsqrtf((float)(vals[k] + 1));   // +1 self loop
            g_count[i]  = 0;                              // self-clean for next replay
        }
        run += vals[k];
    }
}

__global__ void k_fill(const int* __restrict__ ei, int n_edges, int n_nodes) {
    int e = blockIdx.x * blockDim.x + threadIdx.x;
    if (e == 0) g_total = 0;        // self-clean (scan already consumed it)
    if (e < n_edges) {
        int srcv = ei[e];
        int d    = ei[n_edges + e];
        if ((unsigned)d < (unsigned)n_nodes && (unsigned)srcv < (unsigned)n_nodes) {
            int p = atomicAdd(&g_cursor[d], 1);
            g_srcsorted[p] = srcv;
        }
    }
}

// ---------------- fp16 mma / cp.async helpers ----------------
__device__ __forceinline__ uint32_t pack2(float x, float y) {
    __half2 h = __floats2half2_rn(x, y);
    return *reinterpret_cast<uint32_t*>(&h);
}

__device__ __forceinline__ void mma_f16(float c[4], const uint32_t a[4],
                                        uint32_t b0, uint32_t b1) {
    asm volatile(
        "mma.sync.aligned.m16n8k16.row.col.f32.f16.f16.f32 "
        "{%0,%1,%2,%3}, {%4,%5,%6,%7}, {%8,%9}, {%0,%1,%2,%3};"
        : "+f"(c[0]), "+f"(c[1]), "+f"(c[2]), "+f"(c[3])
        : "r"(a[0]), "r"(a[1]), "r"(a[2]), "r"(a[3]), "r"(b0), "r"(b1));
}

__device__ __forceinline__ void cp_async16(void* smem_ptr, const void* gptr, bool valid) {
    uint32_t sa = (uint32_t)__cvta_generic_to_shared(smem_ptr);
    int sz = valid ? 16 : 0;
    asm volatile("cp.async.cg.shared.global [%0], [%1], 16, %2;"
                 :: "r"(sa), "l"(gptr), "r"(sz));
}
#define CP_COMMIT() asm volatile("cp.async.commit_group;" ::: "memory")
#define CP_WAIT(N)  asm volatile("cp.async.wait_group %0;" :: "n"(N) : "memory")

// ---------------- cp.async double-buffered FP16 GEMM, fp16 output, fused dinv ----------------
// g_hnh[m,n] = (half) g_dinv[m] * sum_k A[m,k]*B[k,n]      (m16n8k16 f16, fp32 accumulate)
// B from fp16 transposed device weights: BN==128 -> g_w1h, BN==64 -> g_w2h.
// AHALF=0: A fp32 in gmem (layer-1 x), staged fp32, packed to fp16 at fragment load.
// AHALF=1: A fp16 in gmem (g_x2h), staged fp16, fragments loaded directly.
// TM=64 rows/CTA, 8 warps = 2(M) x 4(N), 3 CTAs/SM. KC=32 per chunk, double-buffered.
#define KC  32
#define TM  64
#define AP  36      // fp32 A pitch (floats)
#define KCP 56      // fp16 pitch (halves) for B and half-A: conflict-free + 16B rows

template <int BN, int AHALF>
__global__ void __launch_bounds__(256, 3)
k_mma(const float* __restrict__ Af, int M, int K) {
    const __half* __restrict__ Bg = (BN == FHID) ? g_w1h : g_w2h;
    const int ABUF_F = TM * AP;      // floats per fp32 A buffer
    const int ABUF_H = TM * KCP;     // halves per fp16 A buffer
    const int BBUF   = BN * KCP;     // halves per B buffer

    extern __shared__ char smraw[];
    float*  Asf0 = reinterpret_cast<float*>(smraw);
    __half* Ash0 = reinterpret_cast<__half*>(smraw);
    __half* Bs0  = reinterpret_cast<__half*>(
        smraw + (AHALF ? 2 * ABUF_H * 2 : 2 * ABUF_F * 4));

    int tid  = threadIdx.x;
    int warp = tid >> 5, lane = tid & 31;
    int wm = warp & 1, wn = warp >> 1;  // 2(M) x 4(N)
    const int WNT = BN / 4;
    const int NF  = WNT / 8;
    int g  = lane >> 2, tg = lane & 3;
    int row0 = blockIdx.x * TM;

    // staging maps
    int arf = tid >> 3, acf = (tid & 7) * 4;   // fp32 A: rows arf, arf+32; 16B cols
    int arh = tid >> 2, akh = (tid & 3) * 8;   // fp16 A: 64 rows, 16B (8-half) cols
    int br  = tid >> 2, bk  = (tid & 3) * 8;   // B: 64 rows/pass

    auto issue = [&](int kc) {
        int k0 = kc * KC;
        if (AHALF) {
            __half* Ash = Ash0 + (kc & 1) * ABUF_H;
            cp_async16(Ash + arh * KCP + akh,
                       g_x2h + (size_t)(row0 + arh) * K + k0 + akh,
                       row0 + arh < M);
        } else {
            float* Asf = Asf0 + (kc & 1) * ABUF_F;
            #pragma unroll
            for (int i = 0; i < 2; i++) {
                int rr = arf + i * 32;
                cp_async16(Asf + rr * AP + acf,
                           Af + (size_t)(row0 + rr) * K + k0 + acf,
                           row0 + rr < M);
            }
        }
        __half* Bs = Bs0 + (kc & 1) * BBUF;
        #pragma unroll
        for (int i = 0; i < BN / 64; i++) {
            int n = br + i * 64;
            cp_async16(Bs + n * KCP + bk,
                       Bg + (size_t)n * K + k0 + bk, true);
        }
    };

    float acc[2][NF][4];
    #pragma unroll
    for (int i = 0; i < 2; i++)
        #pragma unroll
        for (int j = 0; j < NF; j++)
            #pragma unroll
            for (int q = 0; q < 4; q++) acc[i][j][q] = 0.0f;

    issue(0); CP_COMMIT();

    const int NCHUNK = K / KC;
    for (int kc = 0; kc < NCHUNK; kc++) {
        if (kc + 1 < NCHUNK) { issue(kc + 1); CP_COMMIT(); CP_WAIT(1); }
        else                 { CP_WAIT(0); }
        __syncthreads();

        float*  Asf = Asf0 + (kc & 1) * ABUF_F;
        __half* Ash = Ash0 + (kc & 1) * ABUF_H;
        __half* Bs  = Bs0  + (kc & 1) * BBUF;

        #pragma unroll
        for (int kb = 0; kb < KC; kb += 16) {
            uint32_t RA[2][4];
            #pragma unroll
            for (int mf = 0; mf < 2; mf++) {
                int r0 = wm * 32 + mf * 16 + g;   // rows r0, r0+8
                if (AHALF) {
                    RA[mf][0] = *reinterpret_cast<const uint32_t*>(Ash + (r0)     * KCP + kb + tg * 2);
                    RA[mf][1] = *reinterpret_cast<const uint32_t*>(Ash + (r0 + 8) * KCP + kb + tg * 2);
                    RA[mf][2] = *reinterpret_cast<const uint32_t*>(Ash + (r0)     * KCP + kb + tg * 2 + 8);
                    RA[mf][3] = *reinterpret_cast<const uint32_t*>(Ash + (r0 + 8) * KCP + kb + tg * 2 + 8);
                } else {
                    float2 p0 = *reinterpret_cast<const float2*>(Asf + (r0)     * AP + kb + tg * 2);
                    float2 p1 = *reinterpret_cast<const float2*>(Asf + (r0 + 8) * AP + kb + tg * 2);
                    float2 p2 = *reinterpret_cast<const float2*>(Asf + (r0)     * AP + kb + tg * 2 + 8);
                    float2 p3 = *reinterpret_cast<const float2*>(Asf + (r0 + 8) * AP + kb + tg * 2 + 8);
                    RA[mf][0] = pack2(p0.x, p0.y);
                    RA[mf][1] = pack2(p1.x, p1.y);
                    RA[mf][2] = pack2(p2.x, p2.y);
                    RA[mf][3] = pack2(p3.x, p3.y);
                }
            }
            #pragma unroll
            for (int nf = 0; nf < NF; nf++) {
                int bn0 = wn * WNT + nf * 8;
                uint32_t B0 = *reinterpret_cast<const uint32_t*>(Bs + (bn0 + g) * KCP + kb + tg * 2);
                uint32_t B1 = *reinterpret_cast<const uint32_t*>(Bs + (bn0 + g) * KCP + kb + tg * 2 + 8);
                #pragma unroll
                for (int mf = 0; mf < 2; mf++)
                    mma_f16(acc[mf][nf], RA[mf], B0, B1);
            }
        }
        __syncthreads();
    }

    // epilogue: scale by dinv, convert to fp16, store pairs (cc even -> 4B aligned)
    #pragma unroll
    for (int mf = 0; mf < 2; mf++) {
        int r0 = row0 + wm * 32 + mf * 16 + g;
        int r1 = r0 + 8;
        float d0 = (r0 < M) ? g_dinv[r0] : 0.f;
        float d1 = (r1 < M) ? g_dinv[r1] : 0.f;
        #pragma unroll
        for (int nf = 0; nf < NF; nf++) {
            int cc = wn * WNT + nf * 8 + tg * 2;
            if (r0 < M) {
                __half2 h = __floats2half2_rn(acc[mf][nf][0] * d0, acc[mf][nf][1] * d0);
                *reinterpret_cast<__half2*>(g_hnh + (size_t)r0 * BN + cc) = h;
            }
            if (r1 < M) {
                __half2 h = __floats2half2_rn(acc[mf][nf][2] * d1, acc[mf][nf][3] * d1);
                *reinterpret_cast<__half2*>(g_hnh + (size_t)r1 * BN + cc) = h;
            }
        }
    }
}

#define SMEM_GEMM1 (2 * TM * AP * 4 + 2 * FHID * KCP * 2)   // 18432 + 28672 = 47104
#define SMEM_GEMM2 (2 * TM * KCP * 2 + 2 * FOUT * KCP * 2)  // 14336 + 14336 = 28672

// ---------------- fp16 row-load helpers ----------------
__device__ __forceinline__ float4 ld_hn4(const __half* base, size_t row, int pitch, int lane) {
    uint2 raw = *reinterpret_cast<const uint2*>(base + row * pitch + lane * 4);
    __half2 h0 = *reinterpret_cast<const __half2*>(&raw.x);
    __half2 h1 = *reinterpret_cast<const __half2*>(&raw.y);
    float2 f0 = __half22float2(h0);
    float2 f1 = __half22float2(h1);
    return make_float4(f0.x, f0.y, f1.x, f1.y);
}

__device__ __forceinline__ float2 ld_hn2(const __half* base, size_t row, int pitch, int lane) {
    uint32_t raw = *reinterpret_cast<const uint32_t*>(base + row * pitch + lane * 2);
    __half2 h = *reinterpret_cast<const __half2*>(&raw);
    return __half22float2(h);
}

// ---------------- aggregation: one warp per node, MLP-4 fp16 gathers ----------------
// x2h[d] = (half) relu( dinv[d]*(hn[d] + sum hn[s]) + b1 )   (F=128, hn fp16 pre-scaled)
__global__ void k_agg128(const float* __restrict__ bias, int n_nodes) {
    int warp = (blockIdx.x * blockDim.x + threadIdx.x) >> 5;
    int lane = threadIdx.x & 31;
    if (warp >= n_nodes) return;
    int d = warp;
    const __half* hn = g_hnh;
    float4 acc = ld_hn4(hn, (size_t)d, 128, lane);
    float4 acc2 = make_float4(0.f, 0.f, 0.f, 0.f);
    int e = g_start[d], e1 = g_end[d];
    for (; e + 4 <= e1; e += 4) {
        int s0 = g_srcsorted[e],     s1 = g_srcsorted[e + 1];
        int s2 = g_srcsorted[e + 2], s3 = g_srcsorted[e + 3];
        float4 v0 = ld_hn4(hn, (size_t)s0, 128, lane);
        float4 v1 = ld_hn4(hn, (size_t)s1, 128, lane);
        float4 v2 = ld_hn4(hn, (size_t)s2, 128, lane);
        float4 v3 = ld_hn4(hn, (size_t)s3, 128, lane);
        acc.x += v0.x; acc.y += v0.y; acc.z += v0.z; acc.w += v0.w;
        acc2.x += v1.x; acc2.y += v1.y; acc2.z += v1.z; acc2.w += v1.w;
        acc.x += v2.x; acc.y += v2.y; acc.z += v2.z; acc.w += v2.w;
        acc2.x += v3.x; acc2.y += v3.y; acc2.z += v3.z; acc2.w += v3.w;
    }
    for (; e < e1; e++) {
        int s = g_srcsorted[e];
        float4 v = ld_hn4(hn, (size_t)s, 128, lane);
        acc.x += v.x; acc.y += v.y; acc.z += v.z; acc.w += v.w;
    }
    acc.x += acc2.x; acc.y += acc2.y; acc.z += acc2.z; acc.w += acc2.w;
    float dv = g_dinv[d];
    float4 bv = *reinterpret_cast<const float4*>(bias + lane * 4);
    float ox = fmaxf(fmaf(acc.x, dv, bv.x), 0.f);
    float oy = fmaxf(fmaf(acc.y, dv, bv.y), 0.f);
    float oz = fmaxf(fmaf(acc.z, dv, bv.z), 0.f);
    float ow = fmaxf(fmaf(acc.w, dv, bv.w), 0.f);
    uint2 st;
    st.x = pack2(ox, oy);
    st.y = pack2(oz, ow);
    *reinterpret_cast<uint2*>(g_x2h + (size_t)d * 128 + lane * 4) = st;
}

// out[d] = dinv[d]*(hn2[d] + sum hn2[s]) + b2   (F=64, no relu, hn2 fp16 pre-scaled)
__global__ void k_agg64(const float* __restrict__ bias,
                        float* __restrict__ out, int n_nodes) {
    int warp = (blockIdx.x * blockDim.x + threadIdx.x) >> 5;
    int lane = threadIdx.x & 31;
    if (warp >= n_nodes) return;
    int d = warp;
    const __half* hn = g_hnh;
    float2 acc = ld_hn2(hn, (size_t)d, 64, lane);
    float2 acc2 = make_float2(0.f, 0.f);
    int e = g_start[d], e1 = g_end[d];
    for (; e + 4 <= e1; e += 4) {
        int s0 = g_srcsorted[e],     s1 = g_srcsorted[e + 1];
        int s2 = g_srcsorted[e + 2], s3 = g_srcsorted[e + 3];
        float2 v0 = ld_hn2(hn, (size_t)s0, 64, lane);
        float2 v1 = ld_hn2(hn, (size_t)s1, 64, lane);
        float2 v2 = ld_hn2(hn, (size_t)s2, 64, lane);
        float2 v3 = ld_hn2(hn, (size_t)s3, 64, lane);
        acc.x += v0.x; acc.y += v0.y;
        acc2.x += v1.x; acc2.y += v1.y;
        acc.x += v2.x; acc.y += v2.y;
        acc2.x += v3.x; acc2.y += v3.y;
    }
    for (; e < e1; e++) {
        int s = g_srcsorted[e];
        float2 v = ld_hn2(hn, (size_t)s, 64, lane);
        acc.x += v.x; acc.y += v.y;
    }
    acc.x += acc2.x; acc.y += acc2.y;
    float dv = g_dinv[d];
    float2 bv = *reinterpret_cast<const float2*>(bias + lane * 2);
    float2 o;
    o.x = fmaf(acc.x, dv, bv.x);
    o.y = fmaf(acc.y, dv, bv.y);
    *reinterpret_cast<float2*>(out + (size_t)d * 64 + lane * 2) = o;
}

// ---------------- launch (narrow fork: fill overlaps GEMM1) ----------------
extern "C" void kernel_launch(void* const* d_in, const int* in_sizes, int n_in,
                              void* d_out, int out_size) {
    const float* x  = (const float*)d_in[0];
    const int*   ei = (const int*)d_in[1];     // int32 [2, E]
    const float* W1 = (const float*)d_in[2];
    const float* b1 = (const float*)d_in[3];
    const float* W2 = (const float*)d_in[4];
    const float* b2 = (const float*)d_in[5];
    float* out = (float*)d_out;

    int n_nodes = in_sizes[0] / FIN;       // 100000
    int n_edges = in_sizes[1] / 2;         // 600000

    int nb_edges = (n_edges + 255) / 256;
    int nb_scan  = (n_nodes + 1023) / 1024;
    int nb_gemm  = (n_nodes + TM - 1) / TM;
    int nb_agg   = (n_nodes * 32 + 255) / 256;

    // one-time stream/event/attr setup (first call is the uncaptured correctness run)
    static cudaStream_t s2 = nullptr;
    static cudaEvent_t evFork = nullptr, evJoin = nullptr;
    if (!s2) {
        cudaStreamCreateWithFlags(&s2, cudaStreamNonBlocking);
        cudaEventCreateWithFlags(&evFork, cudaEventDisableTiming);
        cudaEventCreateWithFlags(&evJoin, cudaEventDisableTiming);
        cudaFuncSetAttribute(k_mma<FHID, 0>,
                             cudaFuncAttributeMaxDynamicSharedMemorySize, SMEM_GEMM1);
        cudaFuncSetAttribute(k_mma<FOUT, 1>,
                             cudaFuncAttributeMaxDynamicSharedMemorySize, SMEM_GEMM2);
    }

    // ---- CSR: hist (+ fused weight convert/transpose) -> scan, main stream ----
    k_hist<<<nb_edges, 256>>>(ei, W1, W2, n_edges, n_nodes);
    k_scan<<<nb_scan, 256>>>(n_nodes);

    // ---- narrow fork: fill (s2) overlaps GEMM1 (main) ----
    cudaEventRecord(evFork, 0);
    cudaStreamWaitEvent(s2, evFork, 0);
    k_fill<<<nb_edges, 256, 0, s2>>>(ei, n_edges, n_nodes);
    cudaEventRecord(evJoin, s2);

    k_mma<FHID, 0><<<nb_gemm, 256, SMEM_GEMM1>>>(x, n_nodes, FIN);

    cudaStreamWaitEvent(0, evJoin, 0);   // join: adjacency ready

    // ---- layer 1 aggregation ----
    k_agg128<<<nb_agg, 256>>>(b1, n_nodes);

    // ---- layer 2 ----
    k_mma<FOUT, 1><<<nb_gemm, 256, SMEM_GEMM2>>>(nullptr, n_nodes, FHID);
    k_agg64<<<nb_agg, 256>>>(b2, out, n_nodes);
}